// round 17
// baseline (speedup 1.0000x reference)
#include <cuda_runtime.h>

// Layout constants (columns within the 208-wide feature dim)
#define NCOLS        208
#define CPR          52     // float4 chunks per row (208/4)
#define AX_START     163
#define PC_START     171
#define IMM_START    195
#define BRANCH_TAKEN 203
// opcode columns: 88+2=90 (JMP) -> chunk 22 e2; 92 (BZ) -> chunk 23 e0;
//                 93 (BNZ) -> chunk 23 e1.

#define A_THREADS 256
#define A_CPB     512       // chunks per block = 2 per thread
#define MAXBLK    16384

__device__ unsigned g_partials[MAXBLK];
// Monotone arrival counter: zero at module load, NEVER reset. Each execution
// of copy_scan_kernel adds exactly gridDim.x, so the last arrival of any run
// satisfies (ticket+1) % gridDim.x == 0. Deterministic across replays.
__device__ unsigned g_arrive;
__device__ unsigned g_flags;

// Kernel A: flat float4 copy at memcpy speed, with the opcode any()-scan
// embedded (the opcode data is already in registers). Each block stores its
// flag-OR unconditionally (no reset kernel); the LAST block to arrive reduces
// the partials into g_flags. No spin-waits -> no deadlock risk.
__global__ void __launch_bounds__(A_THREADS)
copy_scan_kernel(const float4* __restrict__ xv, float4* __restrict__ yv,
                 int total_chunks)
{
    __shared__ unsigned s_warp[A_THREADS / 32];
    __shared__ unsigned s_last;

    const int tid = threadIdx.x;
    unsigned f = 0u;

    // Normally a single iteration (grid sized to cover everything; the loop
    // only guards pathological nrows > MAXBLK*A_CPB/CPR).
    for (int base = blockIdx.x * A_CPB; base < total_chunks;
         base += gridDim.x * A_CPB) {
        const int c0 = base + tid;
        const int c1 = base + A_THREADS + tid;
        const bool h0 = c0 < total_chunks;
        const bool h1 = c1 < total_chunks;

        float4 v0, v1;
        if (h0) v0 = __ldcs(xv + c0);
        if (h1) v1 = __ldcs(xv + c1);

        if (h0) {
            const int cir = c0 % CPR;
            if (cir == 22) { if (v0.z > 0.5f) f |= 1u; }
            else if (cir == 23) {
                if (v0.x > 0.5f) f |= 2u;
                if (v0.y > 0.5f) f |= 4u;
            }
        }
        if (h1) {
            const int cir = c1 % CPR;
            if (cir == 22) { if (v1.z > 0.5f) f |= 1u; }
            else if (cir == 23) {
                if (v1.x > 0.5f) f |= 2u;
                if (v1.y > 0.5f) f |= 4u;
            }
        }

        if (h0) __stcs(yv + c0, v0);
        if (h1) __stcs(yv + c1, v1);
    }

    // Block-level flag reduction.
    f = __reduce_or_sync(0xFFFFFFFFu, f);
    if ((tid & 31) == 0) s_warp[tid >> 5] = f;
    __syncthreads();

    if (tid == 0) {
        unsigned bf = 0u;
        #pragma unroll
        for (int w = 0; w < A_THREADS / 32; w++) bf |= s_warp[w];
        g_partials[blockIdx.x] = bf;     // unconditional -> no reset needed
        __threadfence();                 // release partial before arriving
        unsigned ticket;
        asm volatile("atom.global.acq_rel.gpu.add.u32 %0, [%1], %2;"
                     : "=r"(ticket) : "l"(&g_arrive), "r"(1u) : "memory");
        s_last = (((ticket + 1u) % gridDim.x) == 0u) ? 1u : 0u;
    }
    __syncthreads();

    if (s_last) {                        // last block: reduce all partials
        unsigned acc = 0u;
        #pragma unroll 4
        for (int i = tid; i < (int)gridDim.x; i += A_THREADS)
            acc |= g_partials[i];
        acc = __reduce_or_sync(0xFFFFFFFFu, acc);
        if ((tid & 31) == 0) s_warp[tid >> 5] = acc;
        __syncthreads();
        if (tid == 0) {
            unsigned bf = 0u;
            #pragma unroll
            for (int w = 0; w < A_THREADS / 32; w++) bf |= s_warp[w];
            g_flags = bf;                // unconditional store
            __threadfence();
        }
    }
}

// Kernel B: thread-per-row patch. If no branch opcode exists anywhere, the
// flat copy is already the correct output and B exits immediately. Otherwise
// overwrite the 8 PC-nibble floats + branch_taken per row. Arithmetic is the
// byte-identical sequential accumulation validated at rel_err = 0.0.
__global__ void __launch_bounds__(256)
patch_kernel(const float* __restrict__ x, float* __restrict__ y, int nrows)
{
    const unsigned flags = g_flags;
    if (flags == 0u) return;             // reference early-return path

    const int r = blockIdx.x * 256 + threadIdx.x;
    if (r >= nrows) return;

    const float* xr = x + (size_t)r * NCOLS;
    float a[8], p[8], im[8];
    #pragma unroll
    for (int n = 0; n < 8; n++) {        // front-batched loads (MLP)
        a[n]  = __ldg(xr + AX_START  + n);
        p[n]  = __ldg(xr + PC_START  + n);
        im[n] = __ldg(xr + IMM_START + n);
    }

    // Sequential n=0..7 accumulation mirrors XLA's unrolled contraction.
    // 16^n is a power of two -> multiplies exact; only add order matters.
    float imm = 0.f, pc = 0.f;
    int   ax  = 0;
    #pragma unroll
    for (int n = 0; n < 8; n++) {
        const float pw = (float)(1 << (4 * n));
        imm = __fadd_rn(imm, __fmul_rn(im[n], pw));
        pc  = __fadd_rn(pc,  __fmul_rn(p[n],  pw));
        ax += (int)a[n] * (1 << (4 * n));     // trunc == astype(int32)
    }

    const bool jmp = (flags & 1u) != 0u;
    const bool bz  = (flags & 2u) != 0u;
    const bool bnz = (flags & 4u) != 0u;
    const bool az  = (ax == 0);

    float new_pc, bt;
    const float pc8 = __fadd_rn(pc, 8.0f);
    if (jmp)      { new_pc = imm;            bt = 1.0f; }
    else if (bz)  { new_pc = az ? imm : pc8; bt = az ? 1.0f : 0.0f; }
    else if (bnz) { new_pc = az ? pc8 : imm; bt = az ? 0.0f : 1.0f; }
    else          { new_pc = pc;             bt = 0.0f; /* unreachable */ }

    const int v = (int)new_pc;           // round-toward-zero == astype(int32)

    float* yr = y + (size_t)r * NCOLS;
    #pragma unroll
    for (int k = 0; k < 8; k++)
        yr[PC_START + k] = (float)((v >> (4 * k)) & 15);
    yr[BRANCH_TAKEN] = bt;
}

extern "C" void kernel_launch(void* const* d_in, const int* in_sizes, int n_in,
                              void* d_out, int out_size) {
    const float* x = (const float*)d_in[0];
    float*       y = (float*)d_out;
    const int nrows        = in_sizes[0] / NCOLS;
    const int total_chunks = in_sizes[0] / 4;          // float4 chunks

    int ablk = (total_chunks + A_CPB - 1) / A_CPB;     // 13312 for this shape
    if (ablk > MAXBLK) ablk = MAXBLK;                  // loop handles the rest

    copy_scan_kernel<<<ablk, A_THREADS>>>(
        (const float4*)x, (float4*)y, total_chunks);

    patch_kernel<<<(nrows + 255) / 256, 256>>>(x, y, nrows);
}